// round 9
// baseline (speedup 1.0000x reference)
#include <cuda_runtime.h>
#include <math.h>
#include <stdint.h>

// IAF, 2 MADE flows, B=4096, D=H=64.
// Identity (verified R1/R4-R8): the reference forward scan is the exact inverse
// of z -> z - shift(z), so density = -0.5*D*log(2pi) - 0.5*sum(lv)
// - 0.5*sum(eps^2); only the inverse pass (8 masked [Bx64]@[64x64] GEMMs) runs.
// R9: 16 warps/block = 2 tiles x 8 n-blocks; tile-scoped named barriers;
// next-layer B-fragments prefetched into registers; biases in smem;
// ping-pong activation buffers; layers fully unrolled.

#define C_DENS (-58.81206612509905f)
#define AST 68

__device__ float2 g_wfrag[8 * 64 * 32];   // 128 KB: [mat][kb*8+nb][lane]

static __device__ __forceinline__ float tf32r(float x) {
    uint32_t y;
    asm("cvt.rna.tf32.f32 %0, %1;" : "=r"(y) : "f"(x));
    return __uint_as_float(y);
}

static __device__ __forceinline__ void mma8(float* d, const float* a, float2 b) {
    asm volatile(
        "mma.sync.aligned.m16n8k8.row.col.f32.tf32.tf32.f32 "
        "{%0,%1,%2,%3}, {%4,%5,%6,%7}, {%8,%9}, {%0,%1,%2,%3};"
        : "+f"(d[0]), "+f"(d[1]), "+f"(d[2]), "+f"(d[3])
        : "r"(__float_as_uint(a[0])), "r"(__float_as_uint(a[1])),
          "r"(__float_as_uint(a[2])), "r"(__float_as_uint(a[3])),
          "r"(__float_as_uint(b.x)), "r"(__float_as_uint(b.y)));
}

static __device__ __forceinline__ void tile_bar(int p) {
    asm volatile("bar.sync %0, 256;" :: "r"(p + 1) : "memory");
}

// ---- Prep: mask + tf32-round + tile weights into B-fragment layout.
__global__ void prep_kernel(const float* __restrict__ W0,
                            const float* __restrict__ W1,
                            const float* __restrict__ W2,
                            const float* __restrict__ Wo) {
    int idx  = blockIdx.x * 256 + threadIdx.x;    // 0..16383
    int lane = idx & 31;
    int frag = (idx >> 5) & 63;
    int mat  = idx >> 11;                          // f*4 + l
    int f = mat >> 2, l = mat & 3;
    int kb = frag >> 3, nb = frag & 7;
    int g = lane >> 2, tig = lane & 3;
    int n = nb * 8 + g;
    const float* src = (l == 0) ? W0 : (l == 1) ? W1 : (l == 2) ? W2 : Wo;
    src += f * 4096;
    int k0 = kb * 8 + tig, k1 = k0 + 4;
    bool m0, m1;
    if (l == 0)      { m0 = (k0 <= n % 63);        m1 = (k1 <= n % 63); }
    else if (l == 3) { m0 = ((k0 % 63) < n);       m1 = ((k1 % 63) < n); }
    else             { m0 = ((k0 % 63) <= n % 63); m1 = ((k1 % 63) <= n % 63); }
    float b0v = m0 ? tf32r(src[k0 * 64 + n]) : 0.0f;
    float b1v = m1 ? tf32r(src[k1 * 64 + n]) : 0.0f;
    g_wfrag[idx] = make_float2(b0v, b1v);
}

__global__ __launch_bounds__(512, 1)
void iaf_main(const float* __restrict__ zm, const float* __restrict__ lv,
              const float* __restrict__ ep,
              const float* __restrict__ bp0, const float* __restrict__ bp1,
              const float* __restrict__ bp2, const float* __restrict__ bpo,
              float* __restrict__ out, int B)
{
    __shared__ float act[2][2][16][AST];   // [buf][tile][row][col]
    __shared__ float zbuf[2][16][AST];     // exact-fp32 z
    __shared__ float bsm[8][64];           // biases, [f*4+l][col]
    const int t = threadIdx.x;

    // ---- Init: biases to smem; z0 = zm + exp(0.5*lv)*eps; density.
    if (t < 512) {
        int mat = t >> 6, j = t & 63;
        int f = mat >> 2, l = mat & 3;
        const float* bl = (l == 0) ? bp0 : (l == 1) ? bp1 : (l == 2) ? bp2 : bpo;
        bsm[mat][j] = bl[f * 64 + j];
    }
    {
        int r = t >> 4, seg = t & 15;          // 32 rows x 16 col-segments
        int pi = r >> 4, ri = r & 15;
        int gr = blockIdx.x * 32 + r;
        bool v = gr < B;
        int col = seg * 4;
        const size_t go = (size_t)gr * 64 + col;
        float4 a = v ? *(const float4*)(zm + go) : make_float4(0,0,0,0);
        float4 b = v ? *(const float4*)(lv + go) : make_float4(0,0,0,0);
        float4 c = v ? *(const float4*)(ep + go) : make_float4(0,0,0,0);
        float4 z4;
        z4.x = a.x + __expf(0.5f * b.x) * c.x;
        z4.y = a.y + __expf(0.5f * b.y) * c.y;
        z4.z = a.z + __expf(0.5f * b.z) * c.z;
        z4.w = a.w + __expf(0.5f * b.w) * c.w;
        *(float4*)&act[0][pi][ri][col] = z4;
        *(float4*)&zbuf[pi][ri][col]   = z4;
        float slv = b.x + b.y + b.z + b.w;
        float se2 = c.x*c.x + c.y*c.y + c.z*c.z + c.w*c.w;
        #pragma unroll
        for (int m = 1; m <= 8; m <<= 1) {
            slv += __shfl_xor_sync(0xffffffffu, slv, m);
            se2 += __shfl_xor_sync(0xffffffffu, se2, m);
        }
        if (seg == 0 && v)
            out[(size_t)B * 64 + gr] = C_DENS - 0.5f * slv - 0.5f * se2;
    }

    const int lane = t & 31, wid = t >> 5;
    const int p = wid >> 3, h = wid & 7;       // tile, n-block (8 cols)
    const int g = lane >> 2, tig = lane & 3;
    const int rowbase = blockIdx.x * 32 + p * 16;

    // Prefetch layer 0 B-fragments (mat order: 4,5,6,7,0,1,2,3).
    float2 Bcur[8], Bnxt[8];
    {
        const float2* wf = g_wfrag + 4 * 2048 + h * 32 + lane;
        #pragma unroll
        for (int kb = 0; kb < 8; ++kb)
            Bcur[kb] = wf[kb * 256];
    }
    __syncthreads();

    // ---- 8 chained layers, fully unrolled; tile-scoped barriers.
    #pragma unroll
    for (int li = 0; li < 8; ++li) {
        const int mat = (li < 4) ? (4 + li) : (li - 4);
        const int l   = mat & 3;
        const int rd  = li & 1, wr = (li + 1) & 1;

        // Prefetch next layer's B-fragments (overlaps this layer's MMAs).
        if (li < 7) {
            const int nmat = (li < 3) ? (5 + li) : (li - 3);
            const float2* wf = g_wfrag + nmat * 2048 + h * 32 + lane;
            #pragma unroll
            for (int kb = 0; kb < 8; ++kb)
                Bnxt[kb] = wf[kb * 256];
        }

        // A-fragments (conflict-free LDS: bank = 4g + tig).
        float Afr[32];
        #pragma unroll
        for (int kb = 0; kb < 8; ++kb) {
            Afr[kb*4+0] = act[rd][p][g][kb*8 + tig];
            Afr[kb*4+1] = act[rd][p][g+8][kb*8 + tig];
            Afr[kb*4+2] = act[rd][p][g][kb*8 + tig + 4];
            Afr[kb*4+3] = act[rd][p][g+8][kb*8 + tig + 4];
        }

        float acc[4];
        #pragma unroll
        for (int i = 0; i < 4; ++i) acc[i] = 0.f;
        #pragma unroll
        for (int kb = 0; kb < 8; ++kb)
            mma8(acc, Afr + kb*4, Bcur[kb]);

        float2 bias = *(const float2*)&bsm[mat][8*h + 2*tig];
        const int c = 8*h + 2*tig;

        if (l < 3) {
            float v0 = fmaxf(acc[0] + bias.x, 0.f);
            float v1 = fmaxf(acc[1] + bias.y, 0.f);
            float v2 = fmaxf(acc[2] + bias.x, 0.f);
            float v3 = fmaxf(acc[3] + bias.y, 0.f);
            *(float2*)&act[wr][p][g][c]   = make_float2(v0, v1);
            *(float2*)&act[wr][p][g+8][c] = make_float2(v2, v3);
            tile_bar(p);
        } else {
            float2 z0 = *(float2*)&zbuf[p][g][c];
            float2 z1 = *(float2*)&zbuf[p][g+8][c];
            float zn0 = z0.x - (acc[0] + bias.x);
            float zn1 = z0.y - (acc[1] + bias.y);
            float zn2 = z1.x - (acc[2] + bias.x);
            float zn3 = z1.y - (acc[3] + bias.y);
            if (li == 3) {
                tile_bar(p);           // zbuf reads done before reversed writes
                const int rc = 62 - c;
                float2 w0 = make_float2(zn1, zn0);
                float2 w1 = make_float2(zn3, zn2);
                *(float2*)&act[wr][p][g][rc]   = w0;
                *(float2*)&act[wr][p][g+8][rc] = w1;
                *(float2*)&zbuf[p][g][rc]      = w0;
                *(float2*)&zbuf[p][g+8][rc]    = w1;
                tile_bar(p);
            } else {
                const int r0 = rowbase + g, r1 = r0 + 8;
                if (r0 < B)
                    *(float2*)(out + (size_t)r0*64 + c) = make_float2(zn0, zn1);
                if (r1 < B)
                    *(float2*)(out + (size_t)r1*64 + c) = make_float2(zn2, zn3);
            }
        }

        // Rotate prefetch buffer (register renames under full unroll).
        #pragma unroll
        for (int i = 0; i < 8; ++i) Bcur[i] = Bnxt[i];
    }
}

extern "C" void kernel_launch(void* const* d_in, const int* in_sizes, int n_in,
                              void* d_out, int out_size) {
    const float* zm = (const float*)d_in[0];
    const float* lv = (const float*)d_in[1];
    const float* ep = (const float*)d_in[2];
    const float* W0 = (const float*)d_in[3];
    const float* b0 = (const float*)d_in[4];
    const float* W1 = (const float*)d_in[5];
    const float* b1 = (const float*)d_in[6];
    const float* W2 = (const float*)d_in[7];
    const float* b2 = (const float*)d_in[8];
    const float* Wo = (const float*)d_in[9];
    const float* bo = (const float*)d_in[10];

    int B = in_sizes[0] / 64;

    prep_kernel<<<64, 256>>>(W0, W1, W2, Wo);
    int grid = (B + 31) / 32;
    iaf_main<<<grid, 512>>>(zm, lv, ep, b0, b1, b2, bo, (float*)d_out, B);
}